// round 1
// baseline (speedup 1.0000x reference)
#include <cuda_runtime.h>

#define NBANDS 31
#define MAXC   34
#define NB     16      // batch
#define NT     1000    // time
#define NF     257     // freq
#define NO     128     // out channels

__constant__ int c_f0[NBANDS] = {
    0, 2, 5, 8, 11, 14, 17, 20, 23, 26, 29,
    32, 40, 48, 56, 64, 72, 80, 88, 96, 104, 112, 120,
    128, 144, 160, 176, 192, 208, 224,
    240
};
__constant__ int c_bw[NBANDS] = {
    2, 3, 3, 3, 3, 3, 3, 3, 3, 3, 3,
    8, 8, 8, 8, 8, 8, 8, 8, 8, 8, 8, 8,
    16, 16, 16, 16, 16, 16, 16,
    17
};

// Scratch (static device memory — allowed; no runtime allocation)
__device__ float d_A [NB * NBANDS * MAXC];
__device__ float d_Bv[NB * NBANDS * MAXC];
__device__ float d_z [(size_t)NBANDS * NB * NT * NO];   // band-major intermediate, 254 MB

// ---------------------------------------------------------------------------
// Kernel 1: per (batch, band) mean/var over the contiguous slab x[b, f0:f0+bw, :, :]
// then fold GN params into affine A, B per channel.
// ---------------------------------------------------------------------------
__global__ __launch_bounds__(256)
void stats_kernel(const float* __restrict__ x,
                  const float* __restrict__ gnw,
                  const float* __restrict__ gnb)
{
    const int b    = blockIdx.x;
    const int band = blockIdx.y;
    const int f0   = c_f0[band];
    const int bw   = c_bw[band];
    const float* p = x + (size_t)(b * NF + f0) * (NT * 2);
    const int n    = bw * NT * 2;

    double s = 0.0, s2 = 0.0;
    for (int i = threadIdx.x; i < n; i += blockDim.x) {
        float v = p[i];
        s  += v;
        s2 += (double)v * (double)v;
    }
    // warp reduce
    for (int off = 16; off; off >>= 1) {
        s  += __shfl_down_sync(0xFFFFFFFFu, s,  off);
        s2 += __shfl_down_sync(0xFFFFFFFFu, s2, off);
    }
    __shared__ double sh0[8], sh1[8];
    const int w = threadIdx.x >> 5, l = threadIdx.x & 31;
    if (l == 0) { sh0[w] = s; sh1[w] = s2; }
    __syncthreads();

    __shared__ float sh_mean, sh_inv;
    if (threadIdx.x == 0) {
        double ts = 0.0, ts2 = 0.0;
        #pragma unroll
        for (int i = 0; i < 8; i++) { ts += sh0[i]; ts2 += sh1[i]; }
        double mean = ts / n;
        double var  = ts2 / n - mean * mean;
        sh_mean = (float)mean;
        sh_inv  = rsqrtf((float)var + 1e-5f);
    }
    __syncthreads();

    const int c = 2 * bw;
    if (threadIdx.x < c) {
        float gw = gnw[band * MAXC + threadIdx.x];
        float gb = gnb[band * MAXC + threadIdx.x];
        float A  = gw * sh_inv;
        int   o  = (b * NBANDS + band) * MAXC + threadIdx.x;
        d_A [o] = A;
        d_Bv[o] = gb - A * sh_mean;
    }
}

// ---------------------------------------------------------------------------
// Kernel 2 (templated on C = 2*bandwidth): per-band fused affine + matvec.
// Block = (band, 32-t tile, batch). Thread computes a 4(o) x 4(t) register
// tile; weights live in registers (fully unrolled); y tile in smem, read as
// warp-uniform broadcasts. Writes band-major z with float4 coalesced stores.
// ---------------------------------------------------------------------------
template <int C>
__global__ __launch_bounds__(256)
void band_gemm(const float* __restrict__ x,
               const float* __restrict__ fcw,
               const float* __restrict__ fcb,
               int band0)
{
    const int band = band0 + blockIdx.x;
    const int t0   = blockIdx.y * 32;
    const int b    = blockIdx.z;
    const int f0   = c_f0[band];
    const int tid  = threadIdx.x;

    __shared__ float As[C], Bs[C];
    __shared__ float ys[32][C];

    if (tid < C) {
        int o = (b * NBANDS + band) * MAXC + tid;
        As[tid] = d_A[o];
        Bs[tid] = d_Bv[o];
    }
    __syncthreads();

    // Load x tile: bw rows of 64 contiguous floats (t0..t0+31, both comps)
    const float* xb = x + ((size_t)(b * NF + f0) * NT + t0) * 2;
    for (int idx = tid; idx < C * 32; idx += 256) {
        const int f  = idx >> 6;       // freq row within band
        const int j  = idx & 63;       // 2*t_local + comp
        const int tl = j >> 1;
        const int k  = 2 * f + (j & 1);
        float v = 0.0f;
        if (t0 + tl < NT) v = xb[f * (NT * 2) + j];
        ys[tl][k] = As[k] * v + Bs[k];
    }
    __syncthreads();

    const int ox = tid & 31;     // 32 o-groups
    const int tg = tid >> 5;     // 8 t-groups (warp-uniform)
    const int ob = ox * 4;

    float w[4][C];
    #pragma unroll
    for (int j = 0; j < 4; j++) {
        const float* wp = fcw + (size_t)(band * NO + ob + j) * MAXC;
        #pragma unroll
        for (int k = 0; k < C; k++) w[j][k] = __ldg(wp + k);
    }

    float acc[4][4];
    #pragma unroll
    for (int j = 0; j < 4; j++) {
        float bias = __ldg(fcb + band * NO + ob + j);
        #pragma unroll
        for (int i = 0; i < 4; i++) acc[j][i] = bias;
    }

    #pragma unroll
    for (int k = 0; k < C; k++) {
        float y0 = ys[tg * 4 + 0][k];
        float y1 = ys[tg * 4 + 1][k];
        float y2 = ys[tg * 4 + 2][k];
        float y3 = ys[tg * 4 + 3][k];
        #pragma unroll
        for (int j = 0; j < 4; j++) {
            acc[j][0] += w[j][k] * y0;
            acc[j][1] += w[j][k] * y1;
            acc[j][2] += w[j][k] * y2;
            acc[j][3] += w[j][k] * y3;
        }
    }

    const size_t zbase = ((size_t)band * NB + b) * NT;
    #pragma unroll
    for (int i = 0; i < 4; i++) {
        const int gt = t0 + tg * 4 + i;
        if (gt < NT) {
            float4 v = make_float4(acc[0][i], acc[1][i], acc[2][i], acc[3][i]);
            *reinterpret_cast<float4*>(&d_z[(zbase + gt) * NO + ob]) = v;
        }
    }
}

// ---------------------------------------------------------------------------
// Kernel 3: assemble out[b][t][o][band] from z[band][b][t][o] via smem tile.
// Reads coalesced (128 contiguous floats per band), writes a fully
// contiguous 3968-float row per (b,t).
// ---------------------------------------------------------------------------
__global__ __launch_bounds__(256)
void assemble(float* __restrict__ out)
{
    const int bt = blockIdx.x;          // 0..B*T-1
    const int b  = bt / NT;
    const int t  = bt - b * NT;

    __shared__ float s[NO * 33];        // [o][band], stride 33 (conflict-free)

    for (int idx = threadIdx.x; idx < NBANDS * NO; idx += 256) {
        const int band = idx >> 7;
        const int o    = idx & 127;
        s[o * 33 + band] = d_z[(((size_t)band * NB + b) * NT + t) * NO + o];
    }
    __syncthreads();

    float* orow = out + (size_t)bt * (NO * NBANDS);
    for (int n = threadIdx.x; n < NO * NBANDS; n += 256) {
        const int o    = n / NBANDS;
        const int band = n - o * NBANDS;
        orow[n] = s[o * 33 + band];
    }
}

// ---------------------------------------------------------------------------
extern "C" void kernel_launch(void* const* d_in, const int* in_sizes, int n_in,
                              void* d_out, int out_size)
{
    const float* x   = (const float*)d_in[0];
    const float* gnw = (const float*)d_in[1];
    const float* gnb = (const float*)d_in[2];
    const float* fcw = (const float*)d_in[3];
    const float* fcb = (const float*)d_in[4];
    float* out = (float*)d_out;

    stats_kernel<<<dim3(16, 31), 256>>>(x, gnw, gnb);

    // band classes by channel count C = 2*bw
    band_gemm<4 ><<<dim3( 1, 32, 16), 256>>>(x, fcw, fcb,  0);  // band 0
    band_gemm<6 ><<<dim3(10, 32, 16), 256>>>(x, fcw, fcb,  1);  // bands 1-10
    band_gemm<16><<<dim3(12, 32, 16), 256>>>(x, fcw, fcb, 11);  // bands 11-22
    band_gemm<32><<<dim3( 7, 32, 16), 256>>>(x, fcw, fcb, 23);  // bands 23-29
    band_gemm<34><<<dim3( 1, 32, 16), 256>>>(x, fcw, fcb, 30);  // band 30

    assemble<<<NB * NT, 256>>>(out);
}

// round 2
// speedup vs baseline: 1.9890x; 1.9890x over previous
#include <cuda_runtime.h>

#define NBANDS 31
#define NB     16
#define NT     1000
#define NF     257
#define NO     128
#define MAXC   34
#define KTOT   536      // sum over bands of roundup4(2*bw)
#define TT     8        // time tile per block

__constant__ int c_f0[NBANDS] = {
    0,2,5,8,11,14,17,20,23,26,29,
    32,40,48,56,64,72,80,88,96,104,112,120,
    128,144,160,176,192,208,224,240
};
__constant__ int c_bw[NBANDS] = {
    2,3,3,3,3,3,3,3,3,3,3,
    8,8,8,8,8,8,8,8,8,8,8,8,
    16,16,16,16,16,16,16,17
};
// aligned k-offset per band (cumsum of roundup4(2*bw))
__constant__ int c_kal[NBANDS] = {
    0,4,12,20,28,36,44,52,60,68,76,
    84,100,116,132,148,164,180,196,212,228,244,260,
    276,308,340,372,404,436,468,500
};
// band-group partition across 8 warp-pairs (balanced by sum C ~64 each)
__constant__ int c_gs[9]  = {0,2,4,6,8,12,16,20,31};
__constant__ int c_gb[31] = {
    30,23,  24,25,  26,27,  28,29,
    11,12,13,14,  15,16,17,18,  19,20,21,22,
    0,1,2,3,4,5,6,7,8,9,10
};

// static scratch
__device__ float d_A2[NB * KTOT];
__device__ float d_B2[NB * KTOT];
__device__ float d_w2[KTOT * NO];   // transposed, zero-padded weights: [kslot][o]

// ---------------------------------------------------------------------------
// Stats: per (b, band) mean/var over x[b, f0:f0+bw, :, :]; fold GN affine into
// per-global-k A, B (A = gw*inv_std, B = gb - A*mu), stored at aligned k index.
// ---------------------------------------------------------------------------
__global__ __launch_bounds__(256)
void stats_kernel(const float* __restrict__ x,
                  const float* __restrict__ gnw,
                  const float* __restrict__ gnb)
{
    const int b    = blockIdx.x;
    const int band = blockIdx.y;
    const int f0   = c_f0[band];
    const int bw   = c_bw[band];
    const float* p = x + (size_t)(b * NF + f0) * (NT * 2);
    const int n    = bw * NT * 2;

    double s = 0.0, s2 = 0.0;
    for (int i = threadIdx.x; i < n; i += blockDim.x) {
        float v = p[i];
        s  += v;
        s2 += (double)v * (double)v;
    }
    for (int off = 16; off; off >>= 1) {
        s  += __shfl_down_sync(0xFFFFFFFFu, s,  off);
        s2 += __shfl_down_sync(0xFFFFFFFFu, s2, off);
    }
    __shared__ double sh0[8], sh1[8];
    const int w = threadIdx.x >> 5, l = threadIdx.x & 31;
    if (l == 0) { sh0[w] = s; sh1[w] = s2; }
    __syncthreads();

    __shared__ float sh_mean, sh_inv;
    if (threadIdx.x == 0) {
        double ts = 0.0, ts2 = 0.0;
        #pragma unroll
        for (int i = 0; i < 8; i++) { ts += sh0[i]; ts2 += sh1[i]; }
        double mean = ts / n;
        double var  = ts2 / n - mean * mean;
        sh_mean = (float)mean;
        sh_inv  = rsqrtf((float)var + 1e-5f);
    }
    __syncthreads();

    const int c = 2 * bw;
    if (threadIdx.x < c) {
        float gw = gnw[band * MAXC + threadIdx.x];
        float gb = gnb[band * MAXC + threadIdx.x];
        float A  = gw * sh_inv;
        int   kg = c_kal[band] + threadIdx.x;
        d_A2[b * KTOT + kg] = A;
        d_B2[b * KTOT + kg] = gb - A * sh_mean;
    }
}

// ---------------------------------------------------------------------------
// Weight prep: transpose fc_w[band][o][c] -> w2[(kal+k)][o], zero-pad k to
// multiple of 4. Makes gemm weight loads contiguous 512B LDG.128 per warp.
// ---------------------------------------------------------------------------
__global__ __launch_bounds__(256)
void prep_w(const float* __restrict__ fcw)
{
    const int band = blockIdx.x;
    const int C    = 2 * c_bw[band];
    const int kp   = (C + 3) & ~3;
    const int kal  = c_kal[band];
    for (int idx = threadIdx.x; idx < kp * NO; idx += blockDim.x) {
        const int k = idx >> 7;
        const int o = idx & 127;
        d_w2[(kal + k) * NO + o] = (k < C) ? fcw[(band * NO + o) * MAXC + k] : 0.0f;
    }
}

// ---------------------------------------------------------------------------
// Fused: build normalized y tile (smem) -> per-warp band GEMMs -> stage
// [t][band][o] in smem -> coalesced final store out[b][t][o][band].
// Block: 512 threads, 8 t per block. Warp w: band-group w>>1, t-half w&1.
// Thread: lane = o-group (4 o's), owns 4 t's.
// ---------------------------------------------------------------------------
#define SOUT_F   (TT * NBANDS * 132)          // 32736 floats
#define SY_F     (TT * KTOT)                  // 4288
#define SMEM_F   (SOUT_F + SY_F + 2 * KTOT)   // + A,B
#define FMA4(acc, wv, sv) \
    acc.x = fmaf(wv.x, sv, acc.x); acc.y = fmaf(wv.y, sv, acc.y); \
    acc.z = fmaf(wv.z, sv, acc.z); acc.w = fmaf(wv.w, sv, acc.w);

__global__ __launch_bounds__(512, 1)
void fused_kernel(const float* __restrict__ x,
                  const float* __restrict__ fcb,
                  float* __restrict__ out)
{
    extern __shared__ float sm[];
    float* s_out = sm;                       // [t][band][132]
    float* s_y   = sm + SOUT_F;              // [t][KTOT]
    float* s_A   = sm + SOUT_F + SY_F;       // [KTOT]
    float* s_B   = s_A + KTOT;

    const int b   = blockIdx.y;
    const int t0  = blockIdx.x * TT;
    const int tid = threadIdx.x;

    // load affine params, zero y staging (pads must be 0: w-pad is 0, but 0*NaN=NaN)
    for (int i = tid; i < KTOT; i += 512) {
        s_A[i] = d_A2[b * KTOT + i];
        s_B[i] = d_B2[b * KTOT + i];
    }
    for (int i = tid; i < TT * KTOT; i += 512) s_y[i] = 0.0f;
    __syncthreads();

    // build normalized y: y[t][kg] = A*x + B. float4 covers (t,t+1)x(re,im).
    for (int idx = tid; idx < NF * 4; idx += 512) {
        const int f = idx >> 2;
        const int q = idx & 3;
        const float4 v = *(const float4*)(x + ((size_t)(b * NF + f) * NT + t0) * 2 + q * 4);
        int band = 0;
        while (band + 1 < NBANDS && f >= c_f0[band + 1]) band++;
        const int kg = c_kal[band] + 2 * (f - c_f0[band]);
        const int ta = 2 * q, tb = 2 * q + 1;
        s_y[ta * KTOT + kg    ] = fmaf(s_A[kg    ], v.x, s_B[kg    ]);
        s_y[ta * KTOT + kg + 1] = fmaf(s_A[kg + 1], v.y, s_B[kg + 1]);
        s_y[tb * KTOT + kg    ] = fmaf(s_A[kg    ], v.z, s_B[kg    ]);
        s_y[tb * KTOT + kg + 1] = fmaf(s_A[kg + 1], v.w, s_B[kg + 1]);
    }
    __syncthreads();

    // per-warp band GEMMs
    const int lane = tid & 31;
    const int warp = tid >> 5;
    const int g    = warp >> 1;
    const int tbas = (warp & 1) * 4;

    for (int bi = c_gs[g]; bi < c_gs[g + 1]; bi++) {
        const int band = c_gb[bi];
        const int kal  = c_kal[band];
        const int kcnt = (2 * c_bw[band] + 3) & ~3;
        const float4* wp = (const float4*)(d_w2 + (size_t)kal * NO) + lane;

        float4 acc0 = __ldg((const float4*)(fcb + band * NO) + lane);
        float4 acc1 = acc0, acc2 = acc0, acc3 = acc0;

        const float* y0 = s_y + (tbas + 0) * KTOT + kal;
        const float* y1 = s_y + (tbas + 1) * KTOT + kal;
        const float* y2 = s_y + (tbas + 2) * KTOT + kal;
        const float* y3 = s_y + (tbas + 3) * KTOT + kal;

        #pragma unroll 2
        for (int k = 0; k < kcnt; k += 4) {
            const float4 w0 = __ldg(wp + (k + 0) * 32);
            const float4 w1 = __ldg(wp + (k + 1) * 32);
            const float4 w2 = __ldg(wp + (k + 2) * 32);
            const float4 w3 = __ldg(wp + (k + 3) * 32);
            float4 ya = *(const float4*)(y0 + k);
            FMA4(acc0, w0, ya.x) FMA4(acc0, w1, ya.y) FMA4(acc0, w2, ya.z) FMA4(acc0, w3, ya.w)
            float4 yb = *(const float4*)(y1 + k);
            FMA4(acc1, w0, yb.x) FMA4(acc1, w1, yb.y) FMA4(acc1, w2, yb.z) FMA4(acc1, w3, yb.w)
            float4 yc = *(const float4*)(y2 + k);
            FMA4(acc2, w0, yc.x) FMA4(acc2, w1, yc.y) FMA4(acc2, w2, yc.z) FMA4(acc2, w3, yc.w)
            float4 yd = *(const float4*)(y3 + k);
            FMA4(acc3, w0, yd.x) FMA4(acc3, w1, yd.y) FMA4(acc3, w2, yd.z) FMA4(acc3, w3, yd.w)
        }

        // stage: lane-contiguous 512B STS.128 per (t, band) -> conflict-free
        *(float4*)&s_out[((tbas + 0) * NBANDS + band) * 132 + 4 * lane] = acc0;
        *(float4*)&s_out[((tbas + 1) * NBANDS + band) * 132 + 4 * lane] = acc1;
        *(float4*)&s_out[((tbas + 2) * NBANDS + band) * 132 + 4 * lane] = acc2;
        *(float4*)&s_out[((tbas + 3) * NBANDS + band) * 132 + 4 * lane] = acc3;
    }
    __syncthreads();

    // final coalesced store: out[b][t][o][band], n = o*31 + band
    for (int t = 0; t < TT; t++) {
        float* orow = out + ((size_t)(b * NT + t0 + t)) * (NO * NBANDS);
        for (int n = tid; n < NO * NBANDS; n += 512) {
            const int o    = n / NBANDS;
            const int band = n - o * NBANDS;
            orow[n] = s_out[(t * NBANDS + band) * 132 + o];
        }
    }
}

// ---------------------------------------------------------------------------
extern "C" void kernel_launch(void* const* d_in, const int* in_sizes, int n_in,
                              void* d_out, int out_size)
{
    const float* x   = (const float*)d_in[0];
    const float* gnw = (const float*)d_in[1];
    const float* gnb = (const float*)d_in[2];
    const float* fcw = (const float*)d_in[3];
    const float* fcb = (const float*)d_in[4];
    float* out = (float*)d_out;

    const int smem_bytes = SMEM_F * 4;
    cudaFuncSetAttribute(fused_kernel,
                         cudaFuncAttributeMaxDynamicSharedMemorySize, smem_bytes);

    stats_kernel<<<dim3(NB, NBANDS), 256>>>(x, gnw, gnb);
    prep_w<<<NBANDS, 256>>>(fcw);
    fused_kernel<<<dim3(NT / TT, NB), 512, smem_bytes>>>(x, fcb, out);
}

// round 3
// speedup vs baseline: 2.8690x; 1.4425x over previous
#include <cuda_runtime.h>

#define NBANDS 31
#define NB     16
#define NT     1000
#define NF     257
#define NO     128
#define MAXC   34
#define KTOT   536      // sum over bands of roundup4(2*bw)
#define TT     8        // time tile per block

__constant__ int c_f0[NBANDS] = {
    0,2,5,8,11,14,17,20,23,26,29,
    32,40,48,56,64,72,80,88,96,104,112,120,
    128,144,160,176,192,208,224,240
};
__constant__ int c_bw[NBANDS] = {
    2,3,3,3,3,3,3,3,3,3,3,
    8,8,8,8,8,8,8,8,8,8,8,8,
    16,16,16,16,16,16,16,17
};
// aligned k-offset per band (cumsum of roundup4(2*bw))
__constant__ int c_kal[NBANDS] = {
    0,4,12,20,28,36,44,52,60,68,76,
    84,100,116,132,148,164,180,196,212,228,244,260,
    276,308,340,372,404,436,468,500
};
// 16 band-groups, one warp each, balanced by sum of padded C (30..34)
__constant__ int c_gs[17] = {0,1,2,3,4,5,6,7,8,10,12,14,16,18,20,26,31};
__constant__ int c_gb[31] = {
    30, 23, 24, 25, 26, 27, 28, 29,
    11,12, 13,14, 15,16, 17,18, 19,20, 21,22,
    0,1,2,3,4,5, 6,7,8,9,10
};

// static scratch
__device__ float d_A2[NB * KTOT];
__device__ float d_B2[NB * KTOT];
__device__ float d_w2[KTOT * NO];   // transposed, zero-padded weights: [kslot][o]

// ---------------------------------------------------------------------------
// Stats: float4 loads, 4 independent fp32 accumulator lanes (high MLP),
// double only for the tiny final combine. Folds GN into per-k affine A, B.
// ---------------------------------------------------------------------------
__global__ __launch_bounds__(512)
void stats_kernel(const float* __restrict__ x,
                  const float* __restrict__ gnw,
                  const float* __restrict__ gnb)
{
    const int b    = blockIdx.x;
    const int band = blockIdx.y;
    const int f0   = c_f0[band];
    const int bw   = c_bw[band];
    const float4* p = (const float4*)(x + (size_t)(b * NF + f0) * (NT * 2));
    const int nv   = bw * NT / 2;        // float4 count (bw*4000/4)
    const int n    = bw * NT * 2;

    float4 a1 = make_float4(0.f, 0.f, 0.f, 0.f);
    float4 a2 = a1;
    for (int i = threadIdx.x; i < nv; i += 512) {
        float4 v = p[i];
        a1.x += v.x; a1.y += v.y; a1.z += v.z; a1.w += v.w;
        a2.x = fmaf(v.x, v.x, a2.x); a2.y = fmaf(v.y, v.y, a2.y);
        a2.z = fmaf(v.z, v.z, a2.z); a2.w = fmaf(v.w, v.w, a2.w);
    }
    float s  = (a1.x + a1.y) + (a1.z + a1.w);
    float s2 = (a2.x + a2.y) + (a2.z + a2.w);
    for (int off = 16; off; off >>= 1) {
        s  += __shfl_down_sync(0xFFFFFFFFu, s,  off);
        s2 += __shfl_down_sync(0xFFFFFFFFu, s2, off);
    }
    __shared__ float sh0[16], sh1[16];
    const int w = threadIdx.x >> 5, l = threadIdx.x & 31;
    if (l == 0) { sh0[w] = s; sh1[w] = s2; }
    __syncthreads();

    __shared__ float sh_mean, sh_inv;
    if (threadIdx.x == 0) {
        double ts = 0.0, ts2 = 0.0;
        #pragma unroll
        for (int i = 0; i < 16; i++) { ts += (double)sh0[i]; ts2 += (double)sh1[i]; }
        double mean = ts / n;
        double var  = ts2 / n - mean * mean;
        sh_mean = (float)mean;
        sh_inv  = rsqrtf((float)var + 1e-5f);
    }
    __syncthreads();

    const int c = 2 * bw;
    if (threadIdx.x < c) {
        float gw = gnw[band * MAXC + threadIdx.x];
        float gb = gnb[band * MAXC + threadIdx.x];
        float A  = gw * sh_inv;
        int   kg = c_kal[band] + threadIdx.x;
        d_A2[b * KTOT + kg] = A;
        d_B2[b * KTOT + kg] = gb - A * sh_mean;
    }
}

// ---------------------------------------------------------------------------
// Weight prep: fc_w[band][o][c] -> w2[(kal+k)][o], zero-padded k.
// ---------------------------------------------------------------------------
__global__ __launch_bounds__(256)
void prep_w(const float* __restrict__ fcw)
{
    const int band = blockIdx.x;
    const int C    = 2 * c_bw[band];
    const int kp   = (C + 3) & ~3;
    const int kal  = c_kal[band];
    for (int idx = threadIdx.x; idx < kp * NO; idx += blockDim.x) {
        const int k = idx >> 7;
        const int o = idx & 127;
        d_w2[(kal + k) * NO + o] = (k < C) ? fcw[(band * NO + o) * MAXC + k] : 0.0f;
    }
}

// ---------------------------------------------------------------------------
// Fused: normalized y tile (smem) -> per-warp band GEMMs (one warp per band
// group, all 8 t's -> each weight row fetched once per block) -> stage
// [t][band][o] -> float4-coalesced final store out[b][t][o][band].
// ---------------------------------------------------------------------------
#define SSTRIDE  132
#define SOUT_F   (TT * NBANDS * SSTRIDE)      // 32736 floats
#define SY_F     (TT * KTOT)                  // 4288
#define SMEM_F   (SOUT_F + SY_F + 2 * KTOT)
#define FMA4(acc, wv, sv) \
    acc.x = fmaf(wv.x, sv, acc.x); acc.y = fmaf(wv.y, sv, acc.y); \
    acc.z = fmaf(wv.z, sv, acc.z); acc.w = fmaf(wv.w, sv, acc.w);

__global__ __launch_bounds__(512, 1)
void fused_kernel(const float* __restrict__ x,
                  const float* __restrict__ fcb,
                  float* __restrict__ out)
{
    extern __shared__ float sm[];
    float* s_out = sm;                       // [t][band][SSTRIDE]
    float* s_y   = sm + SOUT_F;              // [t][KTOT]
    float* s_A   = sm + SOUT_F + SY_F;
    float* s_B   = s_A + KTOT;

    const int b   = blockIdx.y;
    const int t0  = blockIdx.x * TT;
    const int tid = threadIdx.x;

    for (int i = tid; i < KTOT; i += 512) {
        s_A[i] = d_A2[b * KTOT + i];
        s_B[i] = d_B2[b * KTOT + i];
    }
    for (int i = tid; i < TT * KTOT; i += 512) s_y[i] = 0.0f;
    __syncthreads();

    // normalized y: y[t][kg] = A*x + B; float4 covers (t,t+1)x(re,im)
    for (int idx = tid; idx < NF * 4; idx += 512) {
        const int f = idx >> 2;
        const int q = idx & 3;
        const float4 v = *(const float4*)(x + ((size_t)(b * NF + f) * NT + t0) * 2 + q * 4);
        int band = 0;
        while (band + 1 < NBANDS && f >= c_f0[band + 1]) band++;
        const int kg = c_kal[band] + 2 * (f - c_f0[band]);
        const int ta = 2 * q, tb = 2 * q + 1;
        s_y[ta * KTOT + kg    ] = fmaf(s_A[kg    ], v.x, s_B[kg    ]);
        s_y[ta * KTOT + kg + 1] = fmaf(s_A[kg + 1], v.y, s_B[kg + 1]);
        s_y[tb * KTOT + kg    ] = fmaf(s_A[kg    ], v.z, s_B[kg    ]);
        s_y[tb * KTOT + kg + 1] = fmaf(s_A[kg + 1], v.w, s_B[kg + 1]);
    }
    __syncthreads();

    const int lane = tid & 31;
    const int warp = tid >> 5;     // = band group

    for (int bi = c_gs[warp]; bi < c_gs[warp + 1]; bi++) {
        const int band = c_gb[bi];
        const int kal  = c_kal[band];
        const int kcnt = (2 * c_bw[band] + 3) & ~3;
        const float4* wp = (const float4*)(d_w2 + (size_t)kal * NO) + lane;

        float4 acc[TT];
        {
            float4 bias = __ldg((const float4*)(fcb + band * NO) + lane);
            #pragma unroll
            for (int t = 0; t < TT; t++) acc[t] = bias;
        }

        const float* yb = s_y + kal;
        for (int k = 0; k < kcnt; k += 4) {
            const float4 w0 = __ldg(wp + (k + 0) * 32);
            const float4 w1 = __ldg(wp + (k + 1) * 32);
            const float4 w2 = __ldg(wp + (k + 2) * 32);
            const float4 w3 = __ldg(wp + (k + 3) * 32);
            #pragma unroll
            for (int t = 0; t < TT; t++) {
                float4 y = *(const float4*)(yb + t * KTOT + k);
                FMA4(acc[t], w0, y.x)
                FMA4(acc[t], w1, y.y)
                FMA4(acc[t], w2, y.z)
                FMA4(acc[t], w3, y.w)
            }
        }

        #pragma unroll
        for (int t = 0; t < TT; t++)
            *(float4*)&s_out[(t * NBANDS + band) * SSTRIDE + 4 * lane] = acc[t];
    }
    __syncthreads();

    // final store: out[b][t][o][band], float4 STG (n = o*31+band)
    for (int idx = tid; idx < TT * (NO * NBANDS / 4); idx += 512) {
        const int t = idx / (NO * NBANDS / 4);
        const int m = idx - t * (NO * NBANDS / 4);
        const int n = 4 * m;
        float4 v;
        {
            int n0 = n,     o0 = n0 / NBANDS, b0 = n0 - o0 * NBANDS;
            int n1 = n + 1, o1 = n1 / NBANDS, b1 = n1 - o1 * NBANDS;
            int n2 = n + 2, o2 = n2 / NBANDS, b2 = n2 - o2 * NBANDS;
            int n3 = n + 3, o3 = n3 / NBANDS, b3 = n3 - o3 * NBANDS;
            v.x = s_out[(t * NBANDS + b0) * SSTRIDE + o0];
            v.y = s_out[(t * NBANDS + b1) * SSTRIDE + o1];
            v.z = s_out[(t * NBANDS + b2) * SSTRIDE + o2];
            v.w = s_out[(t * NBANDS + b3) * SSTRIDE + o3];
        }
        *(float4*)(out + ((size_t)(b * NT + t0 + t)) * (NO * NBANDS) + n) = v;
    }
}

// ---------------------------------------------------------------------------
extern "C" void kernel_launch(void* const* d_in, const int* in_sizes, int n_in,
                              void* d_out, int out_size)
{
    const float* x   = (const float*)d_in[0];
    const float* gnw = (const float*)d_in[1];
    const float* gnb = (const float*)d_in[2];
    const float* fcw = (const float*)d_in[3];
    const float* fcb = (const float*)d_in[4];
    float* out = (float*)d_out;

    const int smem_bytes = SMEM_F * 4;
    cudaFuncSetAttribute(fused_kernel,
                         cudaFuncAttributeMaxDynamicSharedMemorySize, smem_bytes);

    stats_kernel<<<dim3(NB, NBANDS), 512>>>(x, gnw, gnb);
    prep_w<<<NBANDS, 256>>>(fcw);
    fused_kernel<<<dim3(NT / TT, NB), 512, smem_bytes>>>(x, fcb, out);
}

// round 4
// speedup vs baseline: 3.2303x; 1.1259x over previous
#include <cuda_runtime.h>

#define NBANDS 31
#define NB     16
#define NT     1000
#define NF     257
#define NO     128
#define MAXC   34
#define KTOT   536      // sum of roundup4(2*bw)
#define TT     4        // time tile per block
#define NCH    8        // stats chunks per (b,band)

__constant__ int c_f0[NBANDS] = {
    0,2,5,8,11,14,17,20,23,26,29,
    32,40,48,56,64,72,80,88,96,104,112,120,
    128,144,160,176,192,208,224,240
};
__constant__ int c_bw[NBANDS] = {
    2,3,3,3,3,3,3,3,3,3,3,
    8,8,8,8,8,8,8,8,8,8,8,8,
    16,16,16,16,16,16,16,17
};
// aligned k-offset per band (cumsum of roundup4(2*bw))
__constant__ int c_kal[NBANDS] = {
    0,4,12,20,28,36,44,52,60,68,76,
    84,100,116,132,148,164,180,196,212,228,244,260,
    276,308,340,372,404,436,468,500
};
// 16 band-groups (one warp each); padded-C sums: 36,32x7,32x5,36,40,40
__constant__ int c_gs[17] = {0,1,2,3,4,5,6,7,8,10,12,14,16,18,21,26,31};
__constant__ int c_gb[31] = {
    30,
    23,24,25,26,27,28,29,
    11,12, 13,14, 15,16, 17,18, 19,20,
    21,22,0,
    1,2,3,4,5,
    6,7,8,9,10
};

// static scratch
__device__ float  d_A2[NB * KTOT];
__device__ float  d_B2[NB * KTOT];
__device__ float  d_w2[KTOT * NO];            // transposed, zero-padded weights
__device__ float2 d_ps[NB * NBANDS * NCH];    // partial (sum, sumsq)

// ---------------------------------------------------------------------------
// Stats stage 1: partial sums over a t-chunk of x[b, f0:f0+bw, :, :]
// ---------------------------------------------------------------------------
__global__ __launch_bounds__(256)
void stats1(const float* __restrict__ x)
{
    const int b    = blockIdx.x;
    const int band = blockIdx.y;
    const int ch   = blockIdx.z;
    const int bw   = c_bw[band];
    const float4* p = (const float4*)(x + (size_t)(b * NF + c_f0[band]) * (NT * 2));
    const int nv = bw * NT / 2;
    const int i0 = (int)((long long)nv * ch / NCH);
    const int i1 = (int)((long long)nv * (ch + 1) / NCH);

    float4 a1 = make_float4(0.f, 0.f, 0.f, 0.f);
    float4 a2 = a1;
    for (int i = i0 + threadIdx.x; i < i1; i += 256) {
        float4 v = p[i];
        a1.x += v.x; a1.y += v.y; a1.z += v.z; a1.w += v.w;
        a2.x = fmaf(v.x, v.x, a2.x); a2.y = fmaf(v.y, v.y, a2.y);
        a2.z = fmaf(v.z, v.z, a2.z); a2.w = fmaf(v.w, v.w, a2.w);
    }
    float s  = (a1.x + a1.y) + (a1.z + a1.w);
    float s2 = (a2.x + a2.y) + (a2.z + a2.w);
    for (int off = 16; off; off >>= 1) {
        s  += __shfl_down_sync(0xFFFFFFFFu, s,  off);
        s2 += __shfl_down_sync(0xFFFFFFFFu, s2, off);
    }
    __shared__ float sh0[8], sh1[8];
    const int w = threadIdx.x >> 5, l = threadIdx.x & 31;
    if (l == 0) { sh0[w] = s; sh1[w] = s2; }
    __syncthreads();
    if (threadIdx.x == 0) {
        float ts = 0.f, ts2 = 0.f;
        #pragma unroll
        for (int i = 0; i < 8; i++) { ts += sh0[i]; ts2 += sh1[i]; }
        d_ps[(b * NBANDS + band) * NCH + ch] = make_float2(ts, ts2);
    }
}

// ---------------------------------------------------------------------------
// Stats stage 2: deterministic fp64 combine; fold GN into per-k affine A, B.
// ---------------------------------------------------------------------------
__global__ __launch_bounds__(64)
void stats2(const float* __restrict__ gnw, const float* __restrict__ gnb)
{
    const int b    = blockIdx.x;
    const int band = blockIdx.y;
    const int bw   = c_bw[band];
    const int n    = bw * NT * 2;

    __shared__ float sh_mean, sh_inv;
    if (threadIdx.x == 0) {
        double ts = 0.0, ts2 = 0.0;
        #pragma unroll
        for (int i = 0; i < NCH; i++) {
            float2 v = d_ps[(b * NBANDS + band) * NCH + i];
            ts += (double)v.x; ts2 += (double)v.y;
        }
        double mean = ts / n;
        double var  = ts2 / n - mean * mean;
        sh_mean = (float)mean;
        sh_inv  = rsqrtf((float)var + 1e-5f);
    }
    __syncthreads();

    const int c = 2 * bw;
    if (threadIdx.x < c) {
        float gw = gnw[band * MAXC + threadIdx.x];
        float gb = gnb[band * MAXC + threadIdx.x];
        float A  = gw * sh_inv;
        int   kg = c_kal[band] + threadIdx.x;
        d_A2[b * KTOT + kg] = A;
        d_B2[b * KTOT + kg] = gb - A * sh_mean;
    }
}

// ---------------------------------------------------------------------------
// Weight prep: fc_w[band][o][c] -> w2[(kal+k)][o], zero-padded k.
// ---------------------------------------------------------------------------
__global__ __launch_bounds__(256)
void prep_w(const float* __restrict__ fcw)
{
    const int band = blockIdx.x;
    const int C    = 2 * c_bw[band];
    const int kp   = (C + 3) & ~3;
    const int kal  = c_kal[band];
    for (int idx = threadIdx.x; idx < kp * NO; idx += blockDim.x) {
        const int k = idx >> 7;
        const int o = idx & 127;
        d_w2[(kal + k) * NO + o] = (k < C) ? fcw[(band * NO + o) * MAXC + k] : 0.0f;
    }
}

// ---------------------------------------------------------------------------
// Fused kernel. y stored as duplicated pairs {y,y} so LDS.64 yields a packed
// f32x2 broadcast multiplier; weights/accs are f32x2 pairs from float4 loads.
// ---------------------------------------------------------------------------
#define SSTRIDE  132
#define SOUT_F   (TT * NBANDS * SSTRIDE)      // 16368 floats
#define SY_F     (TT * KTOT * 2)              // 4288 (duplicated pairs)
#define SMEM_F   (SOUT_F + SY_F + 2 * KTOT)   // 21728 floats = 86912 B

#define FMA2(acc, wv, yv) \
    asm("fma.rn.f32x2 %0, %1, %2, %0;" : "+l"(acc) : "l"(wv), "l"(yv));

__global__ __launch_bounds__(512, 2)
void fused_kernel(const float* __restrict__ x,
                  const float* __restrict__ fcb,
                  float* __restrict__ out)
{
    extern __shared__ float sm[];
    float* s_out = sm;                        // [t][band][SSTRIDE]
    float* s_y2  = sm + SOUT_F;               // [t][KTOT] duplicated pairs
    float* s_A   = sm + SOUT_F + SY_F;
    float* s_B   = s_A + KTOT;

    const int b   = blockIdx.y;
    const int t0  = blockIdx.x * TT;
    const int tid = threadIdx.x;

    for (int i = tid; i < KTOT; i += 512) {
        s_A[i] = d_A2[b * KTOT + i];
        s_B[i] = d_B2[b * KTOT + i];
    }
    for (int i = tid; i < SY_F; i += 512) s_y2[i] = 0.0f;
    __syncthreads();

    // y-build: y[t][kg] = A*x + B, written duplicated at (t*KTOT+kg)*2 {+0,+1}
    for (int idx = tid; idx < NF * 2; idx += 512) {
        const int f = idx >> 1;
        const int q = idx & 1;                // q=0 -> t0,t1 ; q=1 -> t2,t3
        const float4 v = *(const float4*)(x + ((size_t)(b * NF + f) * NT + t0) * 2 + q * 4);
        int band = 0;
        while (band + 1 < NBANDS && f >= c_f0[band + 1]) band++;
        const int kg = c_kal[band] + 2 * (f - c_f0[band]);
        const int ta = 2 * q, tb = 2 * q + 1;
        float y;
        y = fmaf(s_A[kg    ], v.x, s_B[kg    ]);
        s_y2[(ta * KTOT + kg    ) * 2] = y; s_y2[(ta * KTOT + kg    ) * 2 + 1] = y;
        y = fmaf(s_A[kg + 1], v.y, s_B[kg + 1]);
        s_y2[(ta * KTOT + kg + 1) * 2] = y; s_y2[(ta * KTOT + kg + 1) * 2 + 1] = y;
        y = fmaf(s_A[kg    ], v.z, s_B[kg    ]);
        s_y2[(tb * KTOT + kg    ) * 2] = y; s_y2[(tb * KTOT + kg    ) * 2 + 1] = y;
        y = fmaf(s_A[kg + 1], v.w, s_B[kg + 1]);
        s_y2[(tb * KTOT + kg + 1) * 2] = y; s_y2[(tb * KTOT + kg + 1) * 2 + 1] = y;
    }
    __syncthreads();

    const int lane = tid & 31;
    const int warp = tid >> 5;     // = band group

    for (int bi = c_gs[warp]; bi < c_gs[warp + 1]; bi++) {
        const int band = c_gb[bi];
        const int kal  = c_kal[band];
        const int kcnt = (2 * c_bw[band] + 3) & ~3;
        // w row k starts at d_w2 + (kal+k)*NO ; lane's float4 = 2 f32x2 pairs
        const ulonglong2* wp = (const ulonglong2*)(d_w2 + (size_t)kal * NO) + lane;

        unsigned long long acc[TT][2];
        {
            ulonglong2 bz = __ldg((const ulonglong2*)(fcb + band * NO) + lane);
            #pragma unroll
            for (int t = 0; t < TT; t++) { acc[t][0] = bz.x; acc[t][1] = bz.y; }
        }

        const unsigned long long* yb =
            (const unsigned long long*)s_y2 + kal;   // index: t*KTOT + k

        for (int k = 0; k < kcnt; k += 4) {
            const ulonglong2 w0 = __ldg(wp + (k + 0) * 32);
            const ulonglong2 w1 = __ldg(wp + (k + 1) * 32);
            const ulonglong2 w2 = __ldg(wp + (k + 2) * 32);
            const ulonglong2 w3 = __ldg(wp + (k + 3) * 32);
            #pragma unroll
            for (int t = 0; t < TT; t++) {
                const ulonglong2 ya = *(const ulonglong2*)(yb + t * KTOT + k);     // y[k],y[k+1]
                const ulonglong2 yc = *(const ulonglong2*)(yb + t * KTOT + k + 2); // y[k+2],y[k+3]
                FMA2(acc[t][0], w0.x, ya.x) FMA2(acc[t][1], w0.y, ya.x)
                FMA2(acc[t][0], w1.x, ya.y) FMA2(acc[t][1], w1.y, ya.y)
                FMA2(acc[t][0], w2.x, yc.x) FMA2(acc[t][1], w2.y, yc.x)
                FMA2(acc[t][0], w3.x, yc.y) FMA2(acc[t][1], w3.y, yc.y)
            }
        }

        #pragma unroll
        for (int t = 0; t < TT; t++) {
            ulonglong2 r; r.x = acc[t][0]; r.y = acc[t][1];
            *(ulonglong2*)&s_out[(t * NBANDS + band) * SSTRIDE + 4 * lane] = r;
        }
    }
    __syncthreads();

    // final store: out[b][t][o][band], float4 STG (n = o*31 + band)
    for (int idx = tid; idx < TT * (NO * NBANDS / 4); idx += 512) {
        const int t = idx / (NO * NBANDS / 4);
        const int m = idx - t * (NO * NBANDS / 4);
        const int n = 4 * m;
        float4 v;
        {
            int n0 = n,     o0 = n0 / NBANDS, b0 = n0 - o0 * NBANDS;
            int n1 = n + 1, o1 = n1 / NBANDS, b1 = n1 - o1 * NBANDS;
            int n2 = n + 2, o2 = n2 / NBANDS, b2 = n2 - o2 * NBANDS;
            int n3 = n + 3, o3 = n3 / NBANDS, b3 = n3 - o3 * NBANDS;
            v.x = s_out[(t * NBANDS + b0) * SSTRIDE + o0];
            v.y = s_out[(t * NBANDS + b1) * SSTRIDE + o1];
            v.z = s_out[(t * NBANDS + b2) * SSTRIDE + o2];
            v.w = s_out[(t * NBANDS + b3) * SSTRIDE + o3];
        }
        *(float4*)(out + ((size_t)(b * NT + t0 + t)) * (NO * NBANDS) + n) = v;
    }
}

// ---------------------------------------------------------------------------
extern "C" void kernel_launch(void* const* d_in, const int* in_sizes, int n_in,
                              void* d_out, int out_size)
{
    const float* x   = (const float*)d_in[0];
    const float* gnw = (const float*)d_in[1];
    const float* gnb = (const float*)d_in[2];
    const float* fcw = (const float*)d_in[3];
    const float* fcb = (const float*)d_in[4];
    float* out = (float*)d_out;

    const int smem_bytes = SMEM_F * 4;
    cudaFuncSetAttribute(fused_kernel,
                         cudaFuncAttributeMaxDynamicSharedMemorySize, smem_bytes);

    stats1<<<dim3(NB, NBANDS, NCH), 256>>>(x);
    stats2<<<dim3(NB, NBANDS), 64>>>(gnw, gnb);
    prep_w<<<NBANDS, 256>>>(fcw);
    fused_kernel<<<dim3(NT / TT, NB), 512, smem_bytes>>>(x, fcb, out);
}

// round 5
// speedup vs baseline: 3.6022x; 1.1152x over previous
#include <cuda_runtime.h>

#define NBANDS 31
#define NB     16
#define NT     1000
#define NF     257
#define NO     128
#define MAXC   34
#define KTOT   536      // sum of roundup4(2*bw)
#define TT     4        // time tile per block
#define NCH    8        // stats chunks per (b,band)
#define OUTW   (NO * NBANDS)   // 3968

__constant__ int c_bw[NBANDS] = {
    2,3,3,3,3,3,3,3,3,3,3,
    8,8,8,8,8,8,8,8,8,8,8,8,
    16,16,16,16,16,16,16,17
};
// aligned k-offset per band (cumsum of roundup4(2*bw))
__constant__ int c_kal[NBANDS] = {
    0,4,12,20,28,36,44,52,60,68,76,
    84,100,116,132,148,164,180,196,212,228,244,260,
    276,308,340,372,404,436,468,500
};
__constant__ int c_f0[NBANDS] = {
    0,2,5,8,11,14,17,20,23,26,29,
    32,40,48,56,64,72,80,88,96,104,112,120,
    128,144,160,176,192,208,224,240
};
// 16 band-groups (one warp each); padded-C sums 32..40
__constant__ int c_gs[17] = {0,1,2,3,4,5,6,7,8,10,12,14,16,18,21,26,31};
__constant__ int c_gb[31] = {
    30,
    23,24,25,26,27,28,29,
    11,12, 13,14, 15,16, 17,18, 19,20,
    21,22,0,
    1,2,3,4,5,
    6,7,8,9,10
};

// static scratch
__device__ float  d_A2[NB * KTOT];
__device__ float  d_B2[NB * KTOT];
__device__ float  d_w2[KTOT * NO];            // interleaved-o weight rows
__device__ float  d_bp[NBANDS * NO];          // interleaved-o bias
__device__ float2 d_ps[NB * NBANDS * NCH];    // partial (sum, sumsq)

// closed-form global-k index for frequency f (component 0)
__device__ __forceinline__ int kg_of_f(int f)
{
    if (f >= 32) return 2 * f + 20;
    if (f >= 2)  return 2 * f - 2 + 2 * ((f + 1) / 3);
    return 2 * f;
}

__device__ __forceinline__ float2 u2f(unsigned long long u)
{
    float2 r;
    asm("mov.b64 {%0,%1}, %2;" : "=f"(r.x), "=f"(r.y) : "l"(u));
    return r;
}

// ---------------------------------------------------------------------------
// Stats stage 1: partial sums over a t-chunk of x[b, f0:f0+bw, :, :]
// ---------------------------------------------------------------------------
__global__ __launch_bounds__(256)
void stats1(const float* __restrict__ x)
{
    const int b    = blockIdx.x;
    const int band = blockIdx.y;
    const int ch   = blockIdx.z;
    const int bw   = c_bw[band];
    const float4* p = (const float4*)(x + (size_t)(b * NF + c_f0[band]) * (NT * 2));
    const int nv = bw * NT / 2;
    const int i0 = (int)((long long)nv * ch / NCH);
    const int i1 = (int)((long long)nv * (ch + 1) / NCH);

    float4 a1 = make_float4(0.f, 0.f, 0.f, 0.f);
    float4 a2 = a1;
    for (int i = i0 + threadIdx.x; i < i1; i += 256) {
        float4 v = p[i];
        a1.x += v.x; a1.y += v.y; a1.z += v.z; a1.w += v.w;
        a2.x = fmaf(v.x, v.x, a2.x); a2.y = fmaf(v.y, v.y, a2.y);
        a2.z = fmaf(v.z, v.z, a2.z); a2.w = fmaf(v.w, v.w, a2.w);
    }
    float s  = (a1.x + a1.y) + (a1.z + a1.w);
    float s2 = (a2.x + a2.y) + (a2.z + a2.w);
    for (int off = 16; off; off >>= 1) {
        s  += __shfl_down_sync(0xFFFFFFFFu, s,  off);
        s2 += __shfl_down_sync(0xFFFFFFFFu, s2, off);
    }
    __shared__ float sh0[8], sh1[8];
    const int w = threadIdx.x >> 5, l = threadIdx.x & 31;
    if (l == 0) { sh0[w] = s; sh1[w] = s2; }
    __syncthreads();
    if (threadIdx.x == 0) {
        float ts = 0.f, ts2 = 0.f;
        #pragma unroll
        for (int i = 0; i < 8; i++) { ts += sh0[i]; ts2 += sh1[i]; }
        d_ps[(b * NBANDS + band) * NCH + ch] = make_float2(ts, ts2);
    }
}

// ---------------------------------------------------------------------------
// Stats stage 2: deterministic fp64 combine; fold GN into per-k affine A, B.
// ---------------------------------------------------------------------------
__global__ __launch_bounds__(64)
void stats2(const float* __restrict__ gnw, const float* __restrict__ gnb)
{
    const int b    = blockIdx.x;
    const int band = blockIdx.y;
    const int bw   = c_bw[band];
    const int n    = bw * NT * 2;

    __shared__ float sh_mean, sh_inv;
    if (threadIdx.x == 0) {
        double ts = 0.0, ts2 = 0.0;
        #pragma unroll
        for (int i = 0; i < NCH; i++) {
            float2 v = d_ps[(b * NBANDS + band) * NCH + i];
            ts += (double)v.x; ts2 += (double)v.y;
        }
        double mean = ts / n;
        double var  = ts2 / n - mean * mean;
        sh_mean = (float)mean;
        sh_inv  = rsqrtf((float)var + 1e-5f);
    }
    __syncthreads();

    const int c = 2 * bw;
    if (threadIdx.x < c) {
        float gw = gnw[band * MAXC + threadIdx.x];
        float gb = gnb[band * MAXC + threadIdx.x];
        float A  = gw * sh_inv;
        int   kg = c_kal[band] + threadIdx.x;
        d_A2[b * KTOT + kg] = A;
        d_B2[b * KTOT + kg] = gb - A * sh_mean;
    }
}

// ---------------------------------------------------------------------------
// Weight/bias prep, interleaved-o: row position 4l+j holds o = l + {0,64,32,96}[j].
// One LDG.128 at 16B*lane then yields lane l's four o's.
// ---------------------------------------------------------------------------
__global__ __launch_bounds__(256)
void prep_w(const float* __restrict__ fcw, const float* __restrict__ fcb)
{
    const int band = blockIdx.x;
    const int C    = 2 * c_bw[band];
    const int kp   = (C + 3) & ~3;
    const int kal  = c_kal[band];
    for (int idx = threadIdx.x; idx < kp * NO; idx += blockDim.x) {
        const int k = idx >> 7;
        const int p = idx & 127;
        const int l = p >> 2;
        const int j = p & 3;
        const int o = l + (j & 1) * 64 + (j >> 1) * 32;   // {0,64,32,96}
        d_w2[(kal + k) * NO + p] = (k < C) ? fcw[(band * NO + o) * MAXC + k] : 0.0f;
    }
    if (threadIdx.x < NO) {
        const int p = threadIdx.x;
        const int l = p >> 2;
        const int j = p & 3;
        const int o = l + (j & 1) * 64 + (j >> 1) * 32;
        d_bp[band * NO + p] = fcb[band * NO + o];
    }
}

// ---------------------------------------------------------------------------
// Fused kernel. y as duplicated {y,y} pairs (f32x2 broadcast via LDS.64);
// s_out stored in EXACT output order [t][n] (n = o*31+band): writer scalar
// STS are conflict-free (31*lane + band + {0,992,1984,2976}, all offsets
// ≡0 mod 32), reader is a flat float4 copy.
// ---------------------------------------------------------------------------
#define SOUT_F   (TT * OUTW)                  // 15872 floats
#define SY_F     (TT * KTOT * 2)              // 4288 (duplicated pairs)
#define SMEM_F   (SOUT_F + SY_F + 2 * KTOT)   // 21232 floats = 84928 B

#define FMA2(acc, wv, yv) \
    asm("fma.rn.f32x2 %0, %1, %2, %0;" : "+l"(acc) : "l"(wv), "l"(yv));

__global__ __launch_bounds__(512, 2)
void fused_kernel(const float* __restrict__ x,
                  float* __restrict__ out)
{
    extern __shared__ float sm[];
    float* s_out = sm;                        // [t][OUTW] exact output order
    float* s_y2  = sm + SOUT_F;               // [t][KTOT] duplicated pairs
    float* s_A   = sm + SOUT_F + SY_F;
    float* s_B   = s_A + KTOT;

    const int b   = blockIdx.y;
    const int t0  = blockIdx.x * TT;
    const int tid = threadIdx.x;

    for (int i = tid; i < KTOT; i += 512) {
        s_A[i] = d_A2[b * KTOT + i];
        s_B[i] = d_B2[b * KTOT + i];
    }
    for (int i = tid; i < SY_F; i += 512) s_y2[i] = 0.0f;
    __syncthreads();

    // y-build: y[t][kg] = A*x + B, duplicated pair written with one STS.64
    for (int idx = tid; idx < NF * 2; idx += 512) {
        const int f = idx >> 1;
        const int q = idx & 1;                // q=0 -> t0,t1 ; q=1 -> t2,t3
        const float4 v = *(const float4*)(x + ((size_t)(b * NF + f) * NT + t0) * 2 + q * 4);
        const int kg = kg_of_f(f);
        const int ta = 2 * q, tb = 2 * q + 1;
        const float A0 = s_A[kg], B0 = s_B[kg];
        const float A1 = s_A[kg + 1], B1 = s_B[kg + 1];
        float y;
        y = fmaf(A0, v.x, B0);
        *(float2*)&s_y2[(ta * KTOT + kg    ) * 2] = make_float2(y, y);
        y = fmaf(A1, v.y, B1);
        *(float2*)&s_y2[(ta * KTOT + kg + 1) * 2] = make_float2(y, y);
        y = fmaf(A0, v.z, B0);
        *(float2*)&s_y2[(tb * KTOT + kg    ) * 2] = make_float2(y, y);
        y = fmaf(A1, v.w, B1);
        *(float2*)&s_y2[(tb * KTOT + kg + 1) * 2] = make_float2(y, y);
    }
    __syncthreads();

    const int lane = tid & 31;
    const int warp = tid >> 5;     // = band group

    for (int bi = c_gs[warp]; bi < c_gs[warp + 1]; bi++) {
        const int band = c_gb[bi];
        const int kal  = c_kal[band];
        const int kcnt = (2 * c_bw[band] + 3) & ~3;
        const ulonglong2* wp = (const ulonglong2*)(d_w2 + (size_t)kal * NO) + lane;

        unsigned long long acc[TT][2];
        {
            // packed bias: (b[l], b[l+64], b[l+32], b[l+96])
            ulonglong2 bz = __ldg((const ulonglong2*)(d_bp + band * NO) + lane);
            #pragma unroll
            for (int t = 0; t < TT; t++) { acc[t][0] = bz.x; acc[t][1] = bz.y; }
        }

        const unsigned long long* yb =
            (const unsigned long long*)s_y2 + kal;   // index: t*KTOT + k

        for (int k = 0; k < kcnt; k += 4) {
            const ulonglong2 w0 = __ldg(wp + (k + 0) * 32);
            const ulonglong2 w1 = __ldg(wp + (k + 1) * 32);
            const ulonglong2 w2 = __ldg(wp + (k + 2) * 32);
            const ulonglong2 w3 = __ldg(wp + (k + 3) * 32);
            #pragma unroll
            for (int t = 0; t < TT; t++) {
                const ulonglong2 ya = *(const ulonglong2*)(yb + t * KTOT + k);
                const ulonglong2 yc = *(const ulonglong2*)(yb + t * KTOT + k + 2);
                FMA2(acc[t][0], w0.x, ya.x) FMA2(acc[t][1], w0.y, ya.x)
                FMA2(acc[t][0], w1.x, ya.y) FMA2(acc[t][1], w1.y, ya.y)
                FMA2(acc[t][0], w2.x, yc.x) FMA2(acc[t][1], w2.y, yc.x)
                FMA2(acc[t][0], w3.x, yc.y) FMA2(acc[t][1], w3.y, yc.y)
            }
        }

        // conflict-free scalar STS: bank = (31*lane + band) mod 32 (distinct/lane)
        #pragma unroll
        for (int t = 0; t < TT; t++) {
            float* so = s_out + t * OUTW + 31 * lane + band;
            float2 pa = u2f(acc[t][0]);     // (o=l,    o=l+64)
            float2 pb = u2f(acc[t][1]);     // (o=l+32, o=l+96)
            so[0]    = pa.x;
            so[1984] = pa.y;                // 31*64
            so[992]  = pb.x;                // 31*32
            so[2976] = pb.y;                // 31*96
        }
    }
    __syncthreads();

    // flat copy: out rows for t0..t0+TT-1 are contiguous in gmem
    {
        const float4* src = (const float4*)s_out;
        float4* dst = (float4*)(out + (size_t)(b * NT + t0) * OUTW);
        #pragma unroll 4
        for (int i = tid; i < TT * OUTW / 4; i += 512)
            dst[i] = src[i];
    }
}

// ---------------------------------------------------------------------------
extern "C" void kernel_launch(void* const* d_in, const int* in_sizes, int n_in,
                              void* d_out, int out_size)
{
    const float* x   = (const float*)d_in[0];
    const float* gnw = (const float*)d_in[1];
    const float* gnb = (const float*)d_in[2];
    const float* fcw = (const float*)d_in[3];
    const float* fcb = (const float*)d_in[4];
    float* out = (float*)d_out;

    const int smem_bytes = SMEM_F * 4;
    cudaFuncSetAttribute(fused_kernel,
                         cudaFuncAttributeMaxDynamicSharedMemorySize, smem_bytes);

    stats1<<<dim3(NB, NBANDS, NCH), 256>>>(x);
    stats2<<<dim3(NB, NBANDS), 64>>>(gnw, gnb);
    prep_w<<<NBANDS, 256>>>(fcw, fcb);
    fused_kernel<<<dim3(NT / TT, NB), 512, smem_bytes>>>(x, out);
}